// round 4
// baseline (speedup 1.0000x reference)
#include <cuda_runtime.h>

// YOLO v1 loss: pred/target (16384, 7, 7, 30) fp32 -> scalar fp32.
// HBM-bound streaming reduction. 192.6 MB total input traffic.

#define NBATCH   16384
#define SGRID    7
#define NCELLS   (NBATCH * SGRID * SGRID)   // 802816
#define CPB      128                        // cells per block
#define NBLOCKS  (NCELLS / CPB)             // 6272, exact
#define L_COORD  5.0f
#define L_NOOBJ  0.5f

__global__ void yolo_zero_out(float* out) {
    if (threadIdx.x == 0) out[0] = 0.0f;
}

__global__ __launch_bounds__(CPB, 8)
void yolo_v1_loss_kernel(const float* __restrict__ pred,
                         const float* __restrict__ targ,
                         float* __restrict__ out) {
    __shared__ float sp[CPB * 30];
    __shared__ float st[CPB * 30];
    __shared__ float warp_sums[CPB / 32];

    const int tid = threadIdx.x;
    const long long cell0 = (long long)blockIdx.x * CPB;

    // Cooperative coalesced staging. 30 floats/cell = 120 B, always 8B-aligned.
    const float2* __restrict__ gp = (const float2*)(pred + cell0 * 30);
    const float2* __restrict__ gt = (const float2*)(targ + cell0 * 30);
    float2* s2p = (float2*)sp;
    float2* s2t = (float2*)st;
    #pragma unroll
    for (int j = tid; j < CPB * 15; j += CPB) {
        s2p[j] = gp[j];
        s2t[j] = gt[j];
    }
    __syncthreads();

    const float* p = sp + tid * 30;
    const float* t = st + tid * 30;

    const float coo = (t[4] > 0.0f) ? 1.0f : 0.0f;

    // no-object confidence loss (both boxes' confidences)
    const float d4 = p[4] - t[4];
    const float d9 = p[9] - t[9];
    const float noo_l = d4 * d4 + d9 * d9;

    // class loss (elements 10..29)
    float cls = 0.0f;
    #pragma unroll
    for (int k = 10; k < 30; k++) {
        const float d = p[k] - t[k];
        cls += d * d;
    }

    // target box 0 corners / area (replicate reference arithmetic exactly)
    const float t0x = t[0], t0y = t[1], t0w = t[2], t0h = t[3];
    const float tltx = t0x - 0.5f * t0w, tlty = t0y - 0.5f * t0h;
    const float trbx = t0x + 0.5f * t0w, trby = t0y + 0.5f * t0h;
    const float area2 = (trbx - tltx) * (trby - tlty);

    float iou[2];
    #pragma unroll
    for (int b = 0; b < 2; b++) {
        const float px = p[b * 5 + 0], py = p[b * 5 + 1];
        const float pw = p[b * 5 + 2], ph = p[b * 5 + 3];
        const float pltx = px - 0.5f * pw, plty = py - 0.5f * ph;
        const float prbx = px + 0.5f * pw, prby = py + 0.5f * ph;
        const float ltx = fmaxf(pltx, tltx), lty = fmaxf(plty, tlty);
        const float rbx = fminf(prbx, trbx), rby = fminf(prby, trby);
        // NOTE: reference indicator is (rb - lt < 0) -> 1.0
        const float ix = ((rbx - ltx) < 0.0f) ? 1.0f : 0.0f;
        const float iy = ((rby - lty) < 0.0f) ? 1.0f : 0.0f;
        const float inter = ix * iy;
        const float area1 = (prbx - pltx) * (prby - plty);
        iou[b] = inter / (area1 + area2 - inter);
    }

    // argmax: first max wins -> idx=1 only when iou1 strictly greater
    const int idx = (iou[1] > iou[0]) ? 1 : 0;
    const float* rp = p + idx * 5;
    const float* rt = t + idx * 5;

    const float dc = rp[4] - rt[4];
    const float contain = dc * dc;

    const float dx = rp[0] - rt[0];
    const float dy = rp[1] - rt[1];

    const bool safe = coo > 0.0f;
    const float swp = sqrtf(safe ? rp[2] : 1.0f);
    const float shp = sqrtf(safe ? rp[3] : 1.0f);
    const float swt = sqrtf(safe ? rt[2] : 1.0f);
    const float sht = sqrtf(safe ? rt[3] : 1.0f);
    const float dw = swp - swt;
    const float dh = shp - sht;

    const float loc = dx * dx + dy * dy + dw * dw + dh * dh;

    float v = coo * (L_COORD * loc + contain + cls)
            + L_NOOBJ * (1.0f - coo) * noo_l;
    v *= (1.0f / (float)NBATCH);

    // block reduction
    #pragma unroll
    for (int off = 16; off > 0; off >>= 1)
        v += __shfl_down_sync(0xffffffffu, v, off);
    if ((tid & 31) == 0) warp_sums[tid >> 5] = v;
    __syncthreads();
    if (tid == 0) {
        float s = 0.0f;
        #pragma unroll
        for (int w = 0; w < CPB / 32; w++) s += warp_sums[w];
        atomicAdd(out, s);
    }
}

extern "C" void kernel_launch(void* const* d_in, const int* in_sizes, int n_in,
                              void* d_out, int out_size) {
    const float* pred = (const float*)d_in[0];
    const float* targ = (const float*)d_in[1];
    float* out = (float*)d_out;

    yolo_zero_out<<<1, 32>>>(out);
    yolo_v1_loss_kernel<<<NBLOCKS, CPB>>>(pred, targ, out);
}